// round 3
// baseline (speedup 1.0000x reference)
#include <cuda_runtime.h>
#include <cuda_bf16.h>
#include <mma.h>
#include <cstdint>

using namespace nvcuda;

// ---------------- problem constants ----------------
#define BB 32768
#define CC 1024
#define CH 256
#define RANKK 16

typedef __nv_bfloat16 bf16;

// ---------------- device scratch (static, no allocation) ----------------
__device__ __align__(16) bf16  g_xn[(size_t)BB * CC];        // LN output, bf16
__device__ __align__(16) bf16  g_dg[(size_t)BB * 512];       // [d | g] pre-GLU
__device__ __align__(16) bf16  g_h1[(size_t)BB * CH];
__device__ __align__(16) bf16  g_t [(size_t)BB * CH];
__device__ __align__(16) bf16  g_h2[(size_t)BB * CH];
__device__ __align__(16) bf16  g_h3[(size_t)BB * CH];

__device__ __align__(16) bf16  g_Wdg[1024 * 512];            // [Wd | Wg] bf16
__device__ __align__(16) float g_bdg[512];
__device__ __align__(16) bf16  g_W1b[256 * 256];
__device__ __align__(16) bf16  g_W2b[256 * 256];
__device__ __align__(16) bf16  g_Wvo[256 * 256];             // Wv @ Wo
__device__ __align__(16) float g_bvo[256];                   // bv @ Wo + bo
__device__ __align__(16) bf16  g_Wu2[256 * 1024];            // Wu + (Wu@Wld)@Wlu
__device__ __align__(16) float g_bu2[1024];                  // bu + (bu@Wld)@Wlu
__device__ __align__(16) float g_T[256 * 16];                // Wu @ Wld

// ---------------- helpers ----------------
__device__ __forceinline__ float gelu_tanh(float x) {
    float x3 = x * x * x;
    return 0.5f * x * (1.0f + tanhf(0.7978845608028654f * (x + 0.044715f * x3)));
}

// ---------------- prep kernels (tiny) ----------------
__global__ void cvt_kernel(const float* __restrict__ src, bf16* __restrict__ dst, int n) {
    int i = blockIdx.x * 256 + threadIdx.x;
    if (i < n) dst[i] = __float2bfloat16(src[i]);
}

__global__ void prep_wdg(const float* __restrict__ Wd, const float* __restrict__ Wg) {
    int idx = blockIdx.x * 256 + threadIdx.x;   // < 1024*512
    int k = idx >> 9, j = idx & 511;
    float v = (j < 256) ? Wd[k * 256 + j] : Wg[k * 256 + (j - 256)];
    g_Wdg[idx] = __float2bfloat16(v);
}

__global__ void prep_bdg(const float* __restrict__ bd, const float* __restrict__ bg) {
    int j = threadIdx.x;  // 512 threads
    g_bdg[j] = (j < 256) ? bd[j] : bg[j - 256];
}

__global__ void prep_wvo(const float* __restrict__ Wv, const float* __restrict__ Wo,
                         const float* __restrict__ bv, const float* __restrict__ bo) {
    __shared__ float row[256];
    int i = blockIdx.x, j = threadIdx.x;
    row[j] = Wv[i * 256 + j];
    __syncthreads();
    float acc = 0.f;
    #pragma unroll 4
    for (int k = 0; k < 256; k++) acc += row[k] * Wo[k * 256 + j];
    g_Wvo[i * 256 + j] = __float2bfloat16(acc);
    if (i == 0) {
        float b = 0.f;
        for (int k = 0; k < 256; k++) b += bv[k] * Wo[k * 256 + j];
        g_bvo[j] = b + bo[j];
    }
}

__global__ void prep_T(const float* __restrict__ Wu, const float* __restrict__ Wld) {
    // T[i][r] = sum_k Wu[i][k] * Wld[k][r]
    int i = blockIdx.x, t = threadIdx.x;      // 256 threads
    int r = t & 15, seg = t >> 4;             // 16 segments of 64
    float acc = 0.f;
    int k0 = seg * 64;
    #pragma unroll 4
    for (int k = k0; k < k0 + 64; k++) acc += Wu[i * 1024 + k] * Wld[k * 16 + r];
    __shared__ float red[256];
    red[t] = acc;
    __syncthreads();
    if (seg == 0) {
        float s = 0.f;
        #pragma unroll
        for (int q = 0; q < 16; q++) s += red[q * 16 + r];
        g_T[i * 16 + r] = s;
    }
}

__global__ void prep_wu2(const float* __restrict__ Wu, const float* __restrict__ Wlu) {
    int i = blockIdx.x;
    int j = blockIdx.y * 256 + threadIdx.x;
    __shared__ float Ti[16];
    if (threadIdx.x < 16) Ti[threadIdx.x] = g_T[i * 16 + threadIdx.x];
    __syncthreads();
    float acc = Wu[i * 1024 + j];
    #pragma unroll
    for (int r = 0; r < 16; r++) acc += Ti[r] * Wlu[r * 1024 + j];
    g_Wu2[i * 1024 + j] = __float2bfloat16(acc);
}

__global__ void prep_bu2(const float* __restrict__ bu, const float* __restrict__ Wld,
                         const float* __restrict__ Wlu) {
    __shared__ float s[16];
    int t = threadIdx.x;  // 1024 threads
    if (t < 16) {
        float a = 0.f;
        for (int k = 0; k < 1024; k++) a += bu[k] * Wld[k * 16 + t];
        s[t] = a;
    }
    __syncthreads();
    float acc = bu[t];
    #pragma unroll
    for (int r = 0; r < 16; r++) acc += s[r] * Wlu[r * 1024 + t];
    g_bu2[t] = acc;
}

// ---------------- LayerNorm: one warp per row ----------------
__global__ void ln_kernel(const float* __restrict__ x, const float* __restrict__ gw,
                          const float* __restrict__ bw) {
    int warp = threadIdx.x >> 5, lane = threadIdx.x & 31;
    int row = blockIdx.x * 8 + warp;
    const float4* xr = (const float4*)(x + (size_t)row * CC);
    float4 v[8];
    float s = 0.f, q = 0.f;
    #pragma unroll
    for (int i = 0; i < 8; i++) {
        v[i] = xr[lane + 32 * i];
        s += v[i].x + v[i].y + v[i].z + v[i].w;
        q += v[i].x * v[i].x + v[i].y * v[i].y + v[i].z * v[i].z + v[i].w * v[i].w;
    }
    #pragma unroll
    for (int o = 16; o; o >>= 1) {
        s += __shfl_xor_sync(0xffffffffu, s, o);
        q += __shfl_xor_sync(0xffffffffu, q, o);
    }
    float mu = s * (1.0f / 1024.0f);
    float var = q * (1.0f / 1024.0f) - mu * mu;
    float rs = rsqrtf(var + 1e-5f);
    uint2* dst = (uint2*)(g_xn + (size_t)row * CC);
    const float4* g4 = (const float4*)gw;
    const float4* b4 = (const float4*)bw;
    #pragma unroll
    for (int i = 0; i < 8; i++) {
        int idx = lane + 32 * i;
        float4 gg = g4[idx], bb = b4[idx];
        float y0 = (v[i].x - mu) * rs * gg.x + bb.x;
        float y1 = (v[i].y - mu) * rs * gg.y + bb.y;
        float y2 = (v[i].z - mu) * rs * gg.z + bb.z;
        float y3 = (v[i].w - mu) * rs * gg.w + bb.w;
        __nv_bfloat162 lo = __floats2bfloat162_rn(y0, y1);
        __nv_bfloat162 hi = __floats2bfloat162_rn(y2, y3);
        uint2 u;
        u.x = *reinterpret_cast<unsigned*>(&lo);
        u.y = *reinterpret_cast<unsigned*>(&hi);
        dst[idx] = u;
    }
}

// ---------------- GLU + depthwise affine ----------------
__global__ void glu_kernel(const float* __restrict__ dw_w, const float* __restrict__ dw_b) {
    int idx = blockIdx.x * 256 + threadIdx.x;   // < B*256
    int i = idx >> 8, c = idx & 255;
    float d  = __bfloat162float(g_dg[(size_t)i * 512 + c]);
    float gv = __bfloat162float(g_dg[(size_t)i * 512 + 256 + c]);
    float sg = 1.0f / (1.0f + expf(-gv));
    float h = d * sg * dw_w[c] + dw_b[c];
    g_h1[idx] = __float2bfloat16(h);
}

// ---------------- generic bf16 WMMA GEMM, 64x128 block tile ----------------
// EPI: 0 = bias (bf16 out), 1 = bias + gelu (bf16 out), 2 = bias + residual mix (fp32 out)
template <int EPI, int N, int K>
__device__ __forceinline__ void gemm_body(const bf16* __restrict__ A,
                                          const bf16* __restrict__ Bw,
                                          const float* __restrict__ bias,
                                          bf16* __restrict__ Cb,
                                          float* __restrict__ Cf,
                                          const float* __restrict__ xres) {
    __shared__ float sC[64 * 132];
    int warp = threadIdx.x >> 5;
    int mw = warp >> 2, nw = warp & 3;                // 2 x 4 warp grid
    int row0 = blockIdx.x * 64 + mw * 32;
    int col0 = blockIdx.y * 128 + nw * 32;

    wmma::fragment<wmma::accumulator, 16, 16, 16, float> c[2][2];
    #pragma unroll
    for (int i = 0; i < 2; i++)
        #pragma unroll
        for (int j = 0; j < 2; j++) wmma::fill_fragment(c[i][j], 0.0f);

    const bf16* Aptr = A + (size_t)row0 * K;
    #pragma unroll 4
    for (int k = 0; k < K; k += 16) {
        wmma::fragment<wmma::matrix_a, 16, 16, 16, bf16, wmma::row_major> a0, a1;
        wmma::fragment<wmma::matrix_b, 16, 16, 16, bf16, wmma::row_major> b0, b1;
        wmma::load_matrix_sync(a0, Aptr + k, K);
        wmma::load_matrix_sync(a1, Aptr + (size_t)16 * K + k, K);
        wmma::load_matrix_sync(b0, Bw + (size_t)k * N + col0, N);
        wmma::load_matrix_sync(b1, Bw + (size_t)k * N + col0 + 16, N);
        wmma::mma_sync(c[0][0], a0, b0, c[0][0]);
        wmma::mma_sync(c[0][1], a0, b1, c[0][1]);
        wmma::mma_sync(c[1][0], a1, b0, c[1][0]);
        wmma::mma_sync(c[1][1], a1, b1, c[1][1]);
    }

    #pragma unroll
    for (int i = 0; i < 2; i++)
        #pragma unroll
        for (int j = 0; j < 2; j++)
            wmma::store_matrix_sync(sC + (mw * 32 + 16 * i) * 132 + nw * 32 + 16 * j,
                                    c[i][j], 132, wmma::mem_row_major);
    __syncthreads();

    #pragma unroll
    for (int e = threadIdx.x; e < 64 * 32; e += 256) {
        int r = e >> 5;
        int c4 = (e & 31) << 2;
        int grow = blockIdx.x * 64 + r;
        int gcol = blockIdx.y * 128 + c4;
        float4 bv = *(const float4*)(bias + gcol);
        float v0 = sC[r * 132 + c4 + 0] + bv.x;
        float v1 = sC[r * 132 + c4 + 1] + bv.y;
        float v2 = sC[r * 132 + c4 + 2] + bv.z;
        float v3 = sC[r * 132 + c4 + 3] + bv.w;
        if (EPI == 1) {
            v0 = gelu_tanh(v0); v1 = gelu_tanh(v1);
            v2 = gelu_tanh(v2); v3 = gelu_tanh(v3);
        }
        if (EPI == 2) {
            float4 xv = *(const float4*)(xres + (size_t)grow * N + gcol);
            float4 o;
            o.x = 0.5f * v0 + 0.5f * xv.x;
            o.y = 0.5f * v1 + 0.5f * xv.y;
            o.z = 0.5f * v2 + 0.5f * xv.z;
            o.w = 0.5f * v3 + 0.5f * xv.w;
            *(float4*)(Cf + (size_t)grow * N + gcol) = o;
        } else {
            __nv_bfloat162 lo = __floats2bfloat162_rn(v0, v1);
            __nv_bfloat162 hi = __floats2bfloat162_rn(v2, v3);
            uint2 u;
            u.x = *reinterpret_cast<unsigned*>(&lo);
            u.y = *reinterpret_cast<unsigned*>(&hi);
            *(uint2*)(Cb + (size_t)grow * N + gcol) = u;
        }
    }
}

__global__ void gemm1_kernel() {                                      // xn @ [Wd|Wg]
    gemm_body<0, 512, 1024>(g_xn, g_Wdg, g_bdg, g_dg, nullptr, nullptr);
}
__global__ void gemm2_kernel(const float* __restrict__ b1) {          // gelu(h1@W1+b1)
    gemm_body<1, 256, 256>(g_h1, g_W1b, b1, g_t, nullptr, nullptr);
}
__global__ void gemm3_kernel(const float* __restrict__ b2) {          // t@W2+b2
    gemm_body<0, 256, 256>(g_t, g_W2b, b2, g_h2, nullptr, nullptr);
}
__global__ void gemm4_kernel() {                                      // h2@Wvo+bvo
    gemm_body<0, 256, 256>(g_h2, g_Wvo, g_bvo, g_h3, nullptr, nullptr);
}
__global__ void gemm5_kernel(float* __restrict__ out, const float* __restrict__ x) {
    gemm_body<2, 1024, 256>(g_h3, g_Wu2, g_bu2, nullptr, out, x);     // up-proj + mix
}

// ---------------- launcher ----------------
extern "C" void kernel_launch(void* const* d_in, const int* in_sizes, int n_in,
                              void* d_out, int out_size) {
    const float* x    = (const float*)d_in[0];
    const float* ln_g = (const float*)d_in[1];
    const float* ln_b = (const float*)d_in[2];
    const float* Wd   = (const float*)d_in[3];
    const float* bd   = (const float*)d_in[4];
    const float* Wg   = (const float*)d_in[5];
    const float* bg   = (const float*)d_in[6];
    const float* dw_w = (const float*)d_in[7];
    const float* dw_b = (const float*)d_in[8];
    const float* W1   = (const float*)d_in[9];
    const float* b1   = (const float*)d_in[10];
    const float* W2   = (const float*)d_in[11];
    const float* b2   = (const float*)d_in[12];
    // d_in[13..16] = Wq,bq,Wk,bk : dead code (softmax over one key == 1)
    const float* Wv   = (const float*)d_in[17];
    const float* bv   = (const float*)d_in[18];
    const float* Wo   = (const float*)d_in[19];
    const float* bo   = (const float*)d_in[20];
    const float* Wu   = (const float*)d_in[21];
    const float* bu   = (const float*)d_in[22];
    const float* Wld  = (const float*)d_in[23];
    const float* Wlu  = (const float*)d_in[24];
    float* out = (float*)d_out;

    // --- weight precompute / folding (tiny) ---
    cvt_kernel<<<(256 * 256 + 255) / 256, 256>>>(W1, g_W1b, 256 * 256);
    cvt_kernel<<<(256 * 256 + 255) / 256, 256>>>(W2, g_W2b, 256 * 256);
    prep_wdg<<<(1024 * 512) / 256, 256>>>(Wd, Wg);
    prep_bdg<<<1, 512>>>(bd, bg);
    prep_wvo<<<256, 256>>>(Wv, Wo, bv, bo);
    prep_T<<<256, 256>>>(Wu, Wld);
    prep_wu2<<<dim3(256, 4), 256>>>(Wu, Wlu);
    prep_bu2<<<1, 1024>>>(bu, Wld, Wlu);

    // --- main pipeline ---
    ln_kernel<<<BB / 8, 256>>>(x, ln_g, ln_b);
    gemm1_kernel<<<dim3(BB / 64, 512 / 128), 256>>>();
    glu_kernel<<<(BB * CH) / 256, 256>>>(dw_w, dw_b);
    gemm2_kernel<<<dim3(BB / 64, 256 / 128), 256>>>(b1);
    gemm3_kernel<<<dim3(BB / 64, 256 / 128), 256>>>(b2);
    gemm4_kernel<<<dim3(BB / 64, 256 / 128), 256>>>();
    gemm5_kernel<<<dim3(BB / 64, 1024 / 128), 256>>>(out, x);
}